// round 17
// baseline (speedup 1.0000x reference)
#include <cuda_runtime.h>
#include <cuda_fp16.h>
#include <cstdint>

// out[i,j] = sigmoid( sum_h W2[h]*relu(A[i,h]+B[j,h]) + b2 )
//   A = Z@W1[:D] + b1, B = Z@W1[D:].
// Identity: relu(a+b) = max(a,-b)+b  =>  logits = sum_h w*max(a,-b) + C_j + b2.
// Single fused persistent kernel:
//   phase 1: prep fp16 A / -B and fp32 C (strided over CTAs)
//   device-wide spin barrier (monotonic ticket counter -> replay-safe, no reset)
//   phase 2: static 3-tile schedule, cp.async double-buffered fp16 tiles,
//            register ping-pong f16x2 math (HMNMX2+HFMA2, 1 slot/pair-h).
#define NN 2048
#define DD 32
#define HH 64
#define GRID 444      // 3 CTAs/SM x 148 SMs -- all co-resident (barrier safety)
#define NTILES 1024

__device__ __half g_Ah [NN * HH];            // A[n][h]   (fp16)
__device__ __half g_nBh[NN * HH];            // -B[n][h]  (fp16)
__device__ float  g_C  [NN];                 // C[j] = sum_h W2[h]*B[j,h]
__device__ unsigned long long g_bar = 0ULL;  // monotonic barrier ticket counter

// acc(h2) += max.f16x2(a,b)*w twice (two h-pairs).
__device__ __forceinline__ void hmax_fma(unsigned& acc,
                                         unsigned alo, unsigned ahi,
                                         unsigned blo, unsigned bhi,
                                         unsigned wlo, unsigned whi) {
    asm("{\n\t"
        ".reg .b32 t0, t1;\n\t"
        "max.f16x2 t0, %1, %3;\n\t"
        "max.f16x2 t1, %2, %4;\n\t"
        "fma.rn.f16x2 %0, t0, %5, %0;\n\t"
        "fma.rn.f16x2 %0, t1, %6, %0;\n\t"
        "}" : "+r"(acc)
            : "r"(alo), "r"(ahi), "r"(blo), "r"(bhi), "r"(wlo), "r"(whi));
}

__device__ __forceinline__ void cp8(void* s, const void* g) {
    unsigned int sa = (unsigned int)__cvta_generic_to_shared(s);
    asm volatile("cp.async.ca.shared.global [%0], [%1], 8;" :: "r"(sa), "l"(g));
}

#define SROWH 68
#define HBUF (64 * SROWH)

__device__ __forceinline__ float sigmoid_fast(float x) {
    float t;
    asm("tanh.approx.f32 %0, %1;" : "=f"(t) : "f"(0.5f * x));
    return fmaf(0.5f, t, 0.5f);
}

__global__ __launch_bounds__(256, 3)
void fused_kernel(const float* __restrict__ Z,
                  const float* __restrict__ W1,
                  const float* __restrict__ b1,
                  const float* __restrict__ W2,
                  const float* __restrict__ b2,
                  float* __restrict__ out) {
    extern __shared__ __half hs[];
    // phase-2 layout (halves): A0 | A1 | B0 | B1 | ws(72)
    __half* ws = hs + 4 * HBUF;
    // phase-1 scratch aliases the A0 buffer (separated by the device barrier)
    float* zsf  = (float*)hs;          // 4 rows x 32 floats
    float* cbuf = (float*)hs + 128;    // 4 rows x 64 floats

    int tid = threadIdx.x;
    int bid = blockIdx.x;
    int tx = tid & 15;   // j lane
    int ty = tid >> 4;   // i lane
    float bias = b2[0];

    // ---------------- phase 1: prep (strided groups of 4 rows) -------------
    for (int nb = bid * 4; nb < NN; nb += GRID * 4) {
        __syncthreads();
        if (tid < 128) zsf[tid] = Z[nb * DD + tid];   // 4 rows x 32 cols
        __syncthreads();
        int ln = tid >> 6;           // 0..3
        int h  = tid & 63;
        int n  = nb + ln;
        float sa = b1[h];
        float sb = 0.0f;
#pragma unroll
        for (int d = 0; d < DD; d++) {
            float z = zsf[ln * DD + d];
            sa = fmaf(z, W1[d * HH + h], sa);
            sb = fmaf(z, W1[(DD + d) * HH + h], sb);
        }
        g_Ah [n * HH + h] = __float2half_rn(sa);
        g_nBh[n * HH + h] = __float2half_rn(-sb);
        cbuf[ln * HH + h] = sb * W2[h];
        __syncthreads();
        if (tid < 4) {
            float c = 0.0f;
#pragma unroll
            for (int k = 0; k < HH; k++) c += cbuf[tid * HH + k];
            g_C[nb + tid] = c;
        }
    }

    // ---------------- device-wide barrier (replay-safe, monotonic) ---------
    __syncthreads();
    if (tid == 0) {
        __threadfence();   // publish this CTA's prep stores
        unsigned long long r = atomicAdd(&g_bar, 1ULL);
        unsigned long long target = (r / GRID + 1ULL) * (unsigned long long)GRID;
        while (*(volatile unsigned long long*)&g_bar < target) __nanosleep(64);
        __threadfence();   // acquire side
    }
    __syncthreads();

    // ---------------- phase 2: pair tiles ----------------------------------
    if (tid < HH) ws[tid] = __float2half_rn(W2[tid]);
    if (tid >= 64 && tid < 72) ws[tid] = __ushort_as_half((unsigned short)0);
    __syncthreads();   // ws visible; phase-1 scratch dead

    int t = bid;
    int p = 0;
    {   // prologue: stage tile bid into buffer 0
        int bj = (t & 31) * 64, bi = (t >> 5) * 64;
        const __half* gA = g_Ah  + bi * HH;
        const __half* gB = g_nBh + bj * HH;
        for (int k = tid; k < 1024; k += 256) {
            int row = k >> 4, ch = (k & 15) * 4;
            cp8(hs + row * SROWH + ch,            gA + row * HH + ch);
            cp8(hs + 2 * HBUF + row * SROWH + ch, gB + row * HH + ch);
        }
        asm volatile("cp.async.commit_group;");
    }

    while (true) {
        int tn = t + GRID;
        __syncthreads();               // prior math on buf p^1 done
        if (tn < NTILES) {             // stage next tile into p^1
            int bj = (tn & 31) * 64, bi = (tn >> 5) * 64;
            const __half* gA = g_Ah  + bi * HH;
            const __half* gB = g_nBh + bj * HH;
            __half* sA = hs + (p ^ 1) * HBUF;
            __half* sB = hs + (2 + (p ^ 1)) * HBUF;
            for (int k = tid; k < 1024; k += 256) {
                int row = k >> 4, ch = (k & 15) * 4;
                cp8(sA + row * SROWH + ch, gA + row * HH + ch);
                cp8(sB + row * SROWH + ch, gB + row * HH + ch);
            }
        }
        asm volatile("cp.async.commit_group;");
        asm volatile("cp.async.wait_group 1;");   // buf p arrived
        __syncthreads();

        int bj = (t & 31) * 64, bi = (t >> 5) * 64;
        const __half* ar = hs + p * HBUF + ty * SROWH;
        const __half* br = hs + (2 + p) * HBUF + tx * SROWH;

        // prefetch the per-j correction (latency hidden by the math loop)
        float Lv[4];
#pragma unroll
        for (int jj = 0; jj < 4; jj++)
            Lv[jj] = __ldg(&g_C[bj + tx + jj * 16]);

        // single half2 accumulator per pair
        unsigned acc[4][4];
#pragma unroll
        for (int ii = 0; ii < 4; ii++)
#pragma unroll
            for (int jj = 0; jj < 4; jj++) acc[ii][jj] = 0u;

        // register ping-pong over 16 steps of 4h
        uint2 ax[4], bx[4], wx;
        uint2 ay[4], by[4], wy;

#define LOADB(AV, BV, WV, h)                                                   \
        do {                                                                   \
            WV = *(const uint2*)(ws + (h));                                    \
            _Pragma("unroll")                                                  \
            for (int ii = 0; ii < 4; ii++)                                     \
                AV[ii] = *(const uint2*)(ar + ii * 16 * SROWH + (h));          \
            _Pragma("unroll")                                                  \
            for (int jj = 0; jj < 4; jj++)                                     \
                BV[jj] = *(const uint2*)(br + jj * 16 * SROWH + (h));          \
        } while (0)

#define COMPB(AV, BV, WV)                                                      \
        do {                                                                   \
            _Pragma("unroll")                                                  \
            for (int jj = 0; jj < 4; jj++)                                     \
                _Pragma("unroll")                                              \
                for (int ii = 0; ii < 4; ii++)                                 \
                    hmax_fma(acc[ii][jj], AV[ii].x, AV[ii].y,                  \
                             BV[jj].x, BV[jj].y, WV.x, WV.y);                  \
        } while (0)

        LOADB(ax, bx, wx, 0);
#pragma unroll
        for (int hb = 0; hb < 64; hb += 8) {
            LOADB(ay, by, wy, hb + 4);
            COMPB(ax, bx, wx);
            LOADB(ax, bx, wx, hb + 8);   // hb=56 loads pad (dead values)
            COMPB(ay, by, wy);
        }
#undef LOADB
#undef COMPB

        // epilogue: fp32 reduce + correction + sigmoid
#pragma unroll
        for (int ii = 0; ii < 4; ii++) {
            int gi = bi + ty + ii * 16;
#pragma unroll
            for (int jj = 0; jj < 4; jj++) {
                int gj = bj + tx + jj * 16;
                float2 u = __half22float2(*(const half2*)&acc[ii][jj]);
                float x = u.x + u.y + Lv[jj] + bias;
                out[gi * NN + gj] = sigmoid_fast(x);   // coalesced across tx
            }
        }

        if (tn >= NTILES) break;
        t = tn;
        p ^= 1;
    }
}

extern "C" void kernel_launch(void* const* d_in, const int* in_sizes, int n_in,
                              void* d_out, int out_size) {
    const float* Z  = (const float*)d_in[0];
    const float* W1 = (const float*)d_in[1];
    const float* b1 = (const float*)d_in[2];
    const float* W2 = (const float*)d_in[3];
    const float* b2 = (const float*)d_in[4];
    float* out = (float*)d_out;

    static const size_t SMEM_BYTES = (4 * HBUF + 72) * sizeof(__half);
    cudaFuncSetAttribute(fused_kernel,
                         cudaFuncAttributeMaxDynamicSharedMemorySize,
                         (int)SMEM_BYTES);

    fused_kernel<<<GRID, 256, SMEM_BYTES>>>(Z, W1, b1, W2, b2, out);
}